// round 12
// baseline (speedup 1.0000x reference)
#include <cuda_runtime.h>
#include <cuda_fp16.h>
#include <cstdint>

#define Ndim 1024
#define Mdim 1024
#define Tdim 64
#define Ddim 128

#define BN 128
#define BM 128
#define BT 2
#define KC 32            // halves per K chunk
#define NKC (Ddim / KC)  // 4
#define PADK 40          // padded smem row stride in halves (80B)
#define THREADS 512

#define A_BYTES (BT * BN * PADK * 2)      // 20480
#define B_BYTES (BT * BM * PADK * 2)      // 20480
#define BUF_BYTES (A_BYTES + B_BYTES)     // 40960
#define SMEM_TOTAL (2 * BUF_BYTES)        // 81920 >= epilogue overlay 66560
#define EPI_T_STRIDE (64 * 130)           // floats per t-plane (64 n-rows x 130)

__device__ float  g_s1[Ndim * Tdim];
__device__ float  g_s2[Mdim * Tdim];
__device__ __half g_h1[(size_t)Ndim * Tdim * Ddim];
__device__ __half g_h2[(size_t)Mdim * Tdim * Ddim];

// ---------------- helpers ----------------
__device__ __forceinline__ uint32_t smem_u32(const void* p) {
    uint32_t a;
    asm("{ .reg .u64 t; cvta.to.shared.u64 t, %1; cvt.u32.u64 %0, t; }" : "=r"(a) : "l"(p));
    return a;
}
__device__ __forceinline__ void cp_async16(uint32_t dst, const void* src) {
    asm volatile("cp.async.cg.shared.global [%0], [%1], 16;" :: "r"(dst), "l"(src));
}
__device__ __forceinline__ void cp_commit() {
    asm volatile("cp.async.commit_group;" ::: "memory");
}
template <int N>
__device__ __forceinline__ void cp_wait() {
    asm volatile("cp.async.wait_group %0;" :: "n"(N) : "memory");
}

__device__ __forceinline__ void mma16816(float* c, uint32_t a0, uint32_t a1,
                                         uint32_t a2, uint32_t a3,
                                         uint32_t b0, uint32_t b1) {
    asm volatile(
        "mma.sync.aligned.m16n8k16.row.col.f32.f16.f16.f32 "
        "{%0,%1,%2,%3}, {%4,%5,%6,%7}, {%8,%9}, {%0,%1,%2,%3};\n"
        : "+f"(c[0]), "+f"(c[1]), "+f"(c[2]), "+f"(c[3])
        : "r"(a0), "r"(a1), "r"(a2), "r"(a3), "r"(b0), "r"(b1));
}

// ---------------------------------------------------------------------------
// Kernel 1: fused fp16 convert + squared row norms. One warp per (row, t).
// ---------------------------------------------------------------------------
__global__ void prep_kernel(const float* __restrict__ X1,
                            const float* __restrict__ X2) {
    int gwarp = (blockIdx.x * blockDim.x + threadIdx.x) >> 5;
    int lane  = threadIdx.x & 31;
    const float* src;
    float* ndst;
    __half* hdst;
    int row;
    if (gwarp < Ndim * Tdim) { src = X1; ndst = g_s1; hdst = g_h1; row = gwarp; }
    else                     { src = X2; ndst = g_s2; hdst = g_h2; row = gwarp - Ndim * Tdim; }
    const float4 v = *((const float4*)(src + (size_t)row * Ddim) + lane);
    __half2 h01 = __floats2half2_rn(v.x, v.y);
    __half2 h23 = __floats2half2_rn(v.z, v.w);
    uint2 packed;
    packed.x = *(uint32_t*)&h01;
    packed.y = *(uint32_t*)&h23;
    *(uint2*)(hdst + (size_t)row * Ddim + lane * 4) = packed;
    float s = v.x * v.x + v.y * v.y + v.z * v.z + v.w * v.w;
    #pragma unroll
    for (int o = 16; o > 0; o >>= 1) s += __shfl_down_sync(0xffffffffu, s, o);
    if (lane == 0) ndst[row] = s;
}

// ---------------------------------------------------------------------------
// Kernel 2: batched cross-GEMM via mma.sync. Big-reuse tile to halve the
// cp.async instruction count (the measured LSU-issue bottleneck).
// CTA: 512 threads = 16 warps = 2 t-planes x 2 n-halves x 4 m-quarters.
// CTA tile: 128n x 128m x 2t. Warp tile: 64n x 32m (one t), 64 accums.
// Grid: t fastest so 8B writes of adjacent-t CTAs merge into full sectors.
// ---------------------------------------------------------------------------
__global__ __launch_bounds__(THREADS, 1)
void cross_mma_kernel(float* __restrict__ Y) {
    extern __shared__ char smem[];
    const uint32_t sbase = smem_u32(smem);

    const int tid  = threadIdx.x;
    const int lane = tid & 31;
    const int wid  = tid >> 5;
    const int tp   = wid >> 3;          // t-plane 0..1
    const int nq   = (wid >> 2) & 1;    // n-half 0..1
    const int mq   = wid & 3;           // m-quarter 0..3

    const int t0 = blockIdx.x * BT;     // t fastest: sector merge across CTAs
    const int m0 = blockIdx.y * BM;
    const int n0 = blockIdx.z * BN;

    const int lr = lane >> 2;          // 0..7
    const int lc = (lane & 3) * 2;     // 0,2,4,6

    float acc[4][4][4];
    #pragma unroll
    for (int i = 0; i < 4; ++i)
        #pragma unroll
        for (int j = 0; j < 4; ++j)
            #pragma unroll
            for (int q = 0; q < 4; ++q) acc[i][j][q] = 0.0f;

    // ---- cp.async loader: 2048 x 16B per stage / 512 thr = 4 each ----
    auto load_stage = [&](int cc, int buf) {
        const uint32_t abase = sbase + buf * BUF_BYTES;
        const uint32_t bbase = abase + A_BYTES;
        #pragma unroll
        for (int it = 0; it < 4; ++it) {
            int i = tid + it * THREADS;          // 0..2047
            if (i < 1024) {
                int k4 = i & 3, n = (i >> 2) & 127, t = i >> 9;
                const __half* g = g_h1 + ((size_t)(n0 + n) * Tdim + (t0 + t)) * Ddim
                                  + cc * KC + k4 * 8;
                cp_async16(abase + t * (BN * PADK * 2) + n * (PADK * 2) + k4 * 16, g);
            } else {
                int j = i - 1024;
                int k4 = j & 3, m = (j >> 2) & 127, t = j >> 9;
                const __half* g = g_h2 + ((size_t)(m0 + m) * Tdim + (t0 + t)) * Ddim
                                  + cc * KC + k4 * 8;
                cp_async16(bbase + t * (BM * PADK * 2) + m * (PADK * 2) + k4 * 16, g);
            }
        }
        cp_commit();
    };

    load_stage(0, 0);

    for (int cc = 0; cc < NKC; ++cc) {
        if (cc + 1 < NKC) {
            load_stage(cc + 1, (cc + 1) & 1);
            cp_wait<1>();     // oldest group (= chunk cc) complete
        } else {
            cp_wait<0>();
        }
        __syncthreads();      // chunk cc visible to all warps

        const int buf = cc & 1;
        const __half* Ah = (const __half*)(smem + buf * BUF_BYTES)
                           + tp * (BN * PADK) + nq * (64 * PADK);
        const __half* Bh = (const __half*)(smem + buf * BUF_BYTES + A_BYTES)
                           + tp * (BM * PADK) + mq * (32 * PADK);

        #pragma unroll
        for (int s = 0; s < 2; ++s) {     // two k16 steps per 32-chunk
            const int kb = s * 16;
            uint32_t b0[4], b1[4];
            #pragma unroll
            for (int mi = 0; mi < 4; ++mi) {
                const __half* bp = Bh + (mi * 8 + lr) * PADK + kb + lc;
                b0[mi] = *(const uint32_t*)(bp);
                b1[mi] = *(const uint32_t*)(bp + 8);
            }
            #pragma unroll
            for (int ni = 0; ni < 4; ++ni) {
                const __half* ap = Ah + (ni * 16 + lr) * PADK + kb + lc;
                uint32_t a0 = *(const uint32_t*)(ap);
                uint32_t a1 = *(const uint32_t*)(ap + 8 * PADK);
                uint32_t a2 = *(const uint32_t*)(ap + 8);
                uint32_t a3 = *(const uint32_t*)(ap + 8 * PADK + 8);
                #pragma unroll
                for (int mi = 0; mi < 4; ++mi)
                    mma16816(acc[ni][mi], a0, a1, a2, a3, b0[mi], b1[mi]);
            }
        }
        __syncthreads();      // all warps done with buf before it is overwritten
    }

    // ---- epilogue: two phases over n-halves; stage [t][64n][130m] ----
    const float invD = 1.0f / (float)Ddim;
    const int tt = t0 + tp;
    float s1a[4], s1b[4], s2a[4], s2b[4];
    #pragma unroll
    for (int ni = 0; ni < 4; ++ni) {
        int ng = n0 + nq * 64 + ni * 16 + lr;
        s1a[ni] = __ldg(&g_s1[ng * Tdim + tt]);
        s1b[ni] = __ldg(&g_s1[(ng + 8) * Tdim + tt]);
    }
    #pragma unroll
    for (int mi = 0; mi < 4; ++mi) {
        int mg = m0 + mq * 32 + mi * 8 + lc;
        s2a[mi] = __ldg(&g_s2[mg * Tdim + tt]);
        s2b[mi] = __ldg(&g_s2[(mg + 1) * Tdim + tt]);
    }

    float* stage = (float*)smem;
    #pragma unroll
    for (int h = 0; h < 2; ++h) {
        if (nq == h) {
            float* plane = stage + tp * EPI_T_STRIDE;
            #pragma unroll
            for (int ni = 0; ni < 4; ++ni) {
                #pragma unroll
                for (int mi = 0; mi < 4; ++mi) {
                    int r  = ni * 16 + lr;              // local n within half
                    int m2 = mq * 32 + mi * 8 + lc;
                    float2 v0, v1;
                    v0.x = (s1a[ni] + s2a[mi] - 2.0f * acc[ni][mi][0]) * invD;
                    v0.y = (s1a[ni] + s2b[mi] - 2.0f * acc[ni][mi][1]) * invD;
                    v1.x = (s1b[ni] + s2a[mi] - 2.0f * acc[ni][mi][2]) * invD;
                    v1.y = (s1b[ni] + s2b[mi] - 2.0f * acc[ni][mi][3]) * invD;
                    *(float2*)(plane + r * 130 + m2)       = v0;
                    *(float2*)(plane + (r + 8) * 130 + m2) = v1;
                }
            }
        }
        __syncthreads();
        // writeback: 64n x 128m (n,m) pairs, 8B (2 t's) each
        #pragma unroll
        for (int it = 0; it < 16; ++it) {
            int p = tid + it * THREADS;    // 0..8191
            int n = p >> 7;
            int m = p & 127;
            float2 w;
            w.x = stage[0 * EPI_T_STRIDE + n * 130 + m];
            w.y = stage[1 * EPI_T_STRIDE + n * 130 + m];
            size_t off = ((size_t)(n0 + h * 64 + n) * Mdim + (m0 + m)) * Tdim + t0;
            *(float2*)(Y + off) = w;
        }
        __syncthreads();
    }
}

// ---------------------------------------------------------------------------
extern "C" void kernel_launch(void* const* d_in, const int* in_sizes, int n_in,
                              void* d_out, int out_size) {
    const float* X1 = (const float*)d_in[0];
    const float* X2 = (const float*)d_in[1];
    float* Y = (float*)d_out;

    int total_warps = 2 * Ndim * Tdim;
    int blocks = (total_warps * 32) / 256;
    prep_kernel<<<blocks, 256>>>(X1, X2);

    cudaFuncSetAttribute(cross_mma_kernel,
                         cudaFuncAttributeMaxDynamicSharedMemorySize, SMEM_TOTAL);
    dim3 grid(Tdim / BT, Mdim / BM, Ndim / BN);   // 32 x 8 x 8 = 2048, t fastest
    cross_mma_kernel<<<grid, THREADS, SMEM_TOTAL>>>(Y);
}